// round 14
// baseline (speedup 1.0000x reference)
#include <cuda_runtime.h>

// ThinVesselLoss: EDT only matters through thin = (0 < 2*dist < 3)
// <=> D2 in {1,2} <=> foreground pixel with >=1 in-bounds 8-neighbor
// background pixel => 3x3 min-stencil on target + weighted BCE + mean.
//
// R14: probe the one unexhausted axis — warp count. 2 px/lane (float2)
// -> 16384 warps (trend: 2048w=9.2us, 4096w=6.7, 8192w=6.3). One wave:
// 1024 blocks x 512 thr. Everything else = proven best body (clamped halo,
// min-stencil, lg2 BCE, packed-u64 atomic finish).

#define B_N 4
#define H_N 512
#define W_N 512
#define NPIX (B_N * H_N * W_N)
#define WPB 16
#define NTHREADS (WPB * 32)                 // 512
#define NWARPS   (B_N * H_N * 8)            // 2048 rows x 8 segs = 16384
#define NBLOCKS  (NWARPS / WPB)             // 1024
#define CNT_ONE  (1ULL << 48)
#define SUM_MASK (CNT_ONE - 1ULL)
#define FIX_SCALE 65536.0
#define LN2 0.6931471805599453

__device__ unsigned long long g_acc;        // zero-init; last block resets

__global__ void __launch_bounds__(NTHREADS)
tv_fused(const float* __restrict__ pred, const float* __restrict__ tgt,
         float* __restrict__ out) {
    const int w    = threadIdx.x >> 5;
    const int lane = threadIdx.x & 31;
    const int g    = blockIdx.x * WPB + w;      // global warp 0..16383
    const int row  = g >> 3;                    // 0..2047 (b*512 + y)
    const int seg  = g & 7;                     // 64-col segment
    const int y    = row & (H_N - 1);

    const int rowoff = row * W_N;               // fits in 22 bits
    const int cglob  = seg * 64 + lane * 2;

    // Clamped halo rows: OOB duplicates are already in-window => no predicates.
    const int offM = rowoff - (y > 0 ? W_N : 0);
    const int offP = rowoff + (y < H_N - 1 ? W_N : 0);

    const float* tY  = tgt + rowoff;
    const float* tYm = tgt + offM;
    const float* tYp = tgt + offP;

    // ---- front-batched loads: 4 x LDG.64 + predicated edge scalars ----
    float2 P  = __ldg(reinterpret_cast<const float2*>(pred + rowoff + cglob));
    float2 C  = __ldg(reinterpret_cast<const float2*>(tY  + cglob));
    float2 A  = __ldg(reinterpret_cast<const float2*>(tYm + cglob));
    float2 Bv = __ldg(reinterpret_cast<const float2*>(tYp + cglob));

    // Segment-edge column (clamped; self-duplicate at image edges).
    const bool isEdge = (lane == 0) | (lane == 31);
    int ecol = (lane == 0) ? (cglob - 1) : (cglob + 2);
    ecol = min(max(ecol, 0), W_N - 1);
    float evm = 1.0f;                           // >0.5: inert
    if (isEdge) {
        float ec = __ldg(tY  + ecol);
        float ea = __ldg(tYm + ecol);
        float eb = __ldg(tYp + ecol);
        evm = fminf(fminf(ea, ec), eb);
    }

    // ---- vertical min per column ----
    float vm0 = fminf(fminf(A.x, C.x), Bv.x);
    float vm1 = fminf(fminf(A.y, C.y), Bv.y);

    // neighbor-lane columns
    float vl = __shfl_up_sync(0xffffffffu, vm1, 1);    // col cglob-1
    float vr = __shfl_down_sync(0xffffffffu, vm0, 1);  // col cglob+2
    if (lane == 0)  vl = evm;
    if (lane == 31) vr = evm;

    // ---- 3-wide horizontal window mins ----
    const float h01 = fminf(vm0, vm1);
    float wn[2] = { fminf(vl, h01), fminf(h01, vr) };

    // ---- weighted BCE in lg2 domain (2 px) ----
    float pv[2] = {P.x, P.y};
    float tv[2] = {C.x, C.y};
    float acc = 0.0f;
#pragma unroll
    for (int i = 0; i < 2; i++) {
        const float t  = tv[i];
        const float l1 = __log2f(pv[i]);          // pred in [.001,.999]:
        const float l2 = __log2f(1.0f - pv[i]);   // -100 clamps provably dead
        const float val = fmaf(t, l1 - l2, l2);   // <= 0
        const float wt = fmaf(2.0f,
            (float)((t > 0.5f) & (wn[i] <= 0.5f)), 1.0f);
        acc = fmaf(wt, val, acc);
    }

    // ---- warp reduction: shfl tree ----
#pragma unroll
    for (int off = 16; off > 0; off >>= 1)
        acc += __shfl_xor_sync(0xffffffffu, acc, off);

    __shared__ float ws[WPB];
    if (lane == 0) ws[w] = acc;
    __syncthreads();

    // ---- packed atomic: fixed-point |sum| + block count in high bits ----
    if (threadIdx.x == 0) {
        float s = 0.0f;
#pragma unroll
        for (int i = 0; i < WPB; i++) s += ws[i];
        unsigned long long contrib =
            ((unsigned long long)__double2ll_rn((double)(-s) * FIX_SCALE)) | CNT_ONE;
        unsigned long long old = atomicAdd(&g_acc, contrib);
        if ((old >> 48) == (unsigned long long)(NBLOCKS - 1)) {
            unsigned long long total = (old + contrib) & SUM_MASK;
            out[0] = (float)((double)total / FIX_SCALE * LN2 / (double)NPIX);
            g_acc = 0ULL;   // all contributors done; reset for next replay
        }
    }
}

extern "C" void kernel_launch(void* const* d_in, const int* in_sizes, int n_in,
                              void* d_out, int out_size) {
    const float* pred = (const float*)d_in[0];
    const float* tgt  = (const float*)d_in[1];
    float* out = (float*)d_out;
    (void)in_sizes; (void)n_in; (void)out_size;

    tv_fused<<<NBLOCKS, NTHREADS>>>(pred, tgt, out);
}